// round 2
// baseline (speedup 1.0000x reference)
#include <cuda_runtime.h>
#include <cuda_bf16.h>
#include <math.h>

// Problem constants
#define BSZ   2
#define LSEQ  4096
#define HDIM  2560
#define CDIM  8192      // D_INNER
#define GNUM  32
#define DHEAD 128
#define DGATE 4096
#define KCONV 4

// ---------------------------------------------------------------------------
// Scratch (static device globals; cudaMalloc is forbidden).
// g_xz (256 MB) is dead after the conv kernel, so the gated activation (128 MB)
// reuses its first half. Total static scratch: ~642 MB.
// ---------------------------------------------------------------------------
__device__ float g_xz[(size_t)BSZ * LSEQ * CDIM];       // pre-conv xz; later: gated
__device__ float g_xs[(size_t)BSZ * LSEQ * DGATE];      // silu(conv x half)
__device__ float g_zs[(size_t)BSZ * LSEQ * DGATE];      // silu(conv z half)
__device__ float g_ys[(size_t)BSZ * LSEQ * DGATE];      // scan output
__device__ float g_Bc[(size_t)BSZ * LSEQ * GNUM];
__device__ float g_Cc[(size_t)BSZ * LSEQ * GNUM];

// ---------------------------------------------------------------------------
// SGEMM NT: C[M,N] = A[M,K] * B[N,K]^T   (A,B,C row-major, fp32)
// 128x128 block, BK=8, 256 threads, 8x8 per-thread microtile.
// Requires M%128==0, N%128==0, K%8==0.
// ---------------------------------------------------------------------------
__global__ __launch_bounds__(256) void sgemm_nt(
    const float* __restrict__ A, const float* __restrict__ B,
    float* __restrict__ C, int M, int N, int K)
{
    __shared__ float As[8][128];
    __shared__ float Bs[8][128];

    const int tid  = threadIdx.x;
    const int lrow = tid >> 1;          // 0..127
    const int lk   = (tid & 1) * 4;     // 0 or 4
    const int tx   = tid & 15;          // n dir (0..15)
    const int ty   = tid >> 4;          // m dir (0..15)

    const float* Ap = A + (size_t)(blockIdx.y * 128 + lrow) * K + lk;
    const float* Bp = B + (size_t)(blockIdx.x * 128 + lrow) * K + lk;

    float acc[8][8];
#pragma unroll
    for (int i = 0; i < 8; i++)
#pragma unroll
        for (int j = 0; j < 8; j++) acc[i][j] = 0.f;

    for (int k0 = 0; k0 < K; k0 += 8) {
        float4 a4 = *(const float4*)(Ap + k0);
        float4 b4 = *(const float4*)(Bp + k0);
        __syncthreads();
        As[lk + 0][lrow] = a4.x; As[lk + 1][lrow] = a4.y;
        As[lk + 2][lrow] = a4.z; As[lk + 3][lrow] = a4.w;
        Bs[lk + 0][lrow] = b4.x; Bs[lk + 1][lrow] = b4.y;
        Bs[lk + 2][lrow] = b4.z; Bs[lk + 3][lrow] = b4.w;
        __syncthreads();
#pragma unroll
        for (int kk = 0; kk < 8; kk++) {
            float ar[8], br[8];
            *(float4*)(ar)     = *(const float4*)&As[kk][ty * 8];
            *(float4*)(ar + 4) = *(const float4*)&As[kk][ty * 8 + 4];
            *(float4*)(br)     = *(const float4*)&Bs[kk][tx * 8];
            *(float4*)(br + 4) = *(const float4*)&Bs[kk][tx * 8 + 4];
#pragma unroll
            for (int i = 0; i < 8; i++)
#pragma unroll
                for (int j = 0; j < 8; j++)
                    acc[i][j] = fmaf(ar[i], br[j], acc[i][j]);
        }
    }

#pragma unroll
    for (int i = 0; i < 8; i++) {
        float* Cp = C + (size_t)(blockIdx.y * 128 + ty * 8 + i) * N
                      + blockIdx.x * 128 + tx * 8;
        *(float4*)(Cp)     = make_float4(acc[i][0], acc[i][1], acc[i][2], acc[i][3]);
        *(float4*)(Cp + 4) = make_float4(acc[i][4], acc[i][5], acc[i][6], acc[i][7]);
    }
}

// ---------------------------------------------------------------------------
// B/C coefficient projections: [M,32] = hidden[M,2560] @ W_b.T, and W_a.T.
// Block computes 32 m-rows x all 64 outputs. 256 threads.
// ---------------------------------------------------------------------------
__global__ __launch_bounds__(256) void coeff_kernel(
    const float* __restrict__ hid, const float* __restrict__ Wb,
    const float* __restrict__ Wa, float* __restrict__ Bc, float* __restrict__ Cc)
{
    __shared__ float sh[32][65];
    __shared__ float sw[64][65];

    const int tid = threadIdx.x;
    const int m0  = blockIdx.x * 32;
    const int tm  = tid & 31;       // m within tile
    const int tj4 = tid >> 5;       // 0..7  -> output group of 8

    const int lr_h = tid >> 3;          // 0..31
    const int lc_h = (tid & 7) * 8;     // 0..56
    const int lr_w = tid >> 2;          // 0..63
    const int lc_w = (tid & 3) * 16;    // 0..48
    const float* wrow = (lr_w < 32) ? (Wb + (size_t)lr_w * HDIM)
                                    : (Wa + (size_t)(lr_w - 32) * HDIM);
    const float* hrow = hid + (size_t)(m0 + lr_h) * HDIM;

    float acc[8];
#pragma unroll
    for (int j = 0; j < 8; j++) acc[j] = 0.f;

    for (int k0 = 0; k0 < HDIM; k0 += 64) {
        __syncthreads();
#pragma unroll
        for (int i = 0; i < 8; i++)  sh[lr_h][lc_h + i] = hrow[k0 + lc_h + i];
#pragma unroll
        for (int i = 0; i < 16; i++) sw[lr_w][lc_w + i] = wrow[k0 + lc_w + i];
        __syncthreads();
#pragma unroll
        for (int k = 0; k < 64; k++) {
            float hv = sh[tm][k];
#pragma unroll
            for (int jj = 0; jj < 8; jj++)
                acc[jj] = fmaf(hv, sw[tj4 * 8 + jj][k], acc[jj]);
        }
    }

#pragma unroll
    for (int jj = 0; jj < 8; jj++) {
        int j = tj4 * 8 + jj;
        if (j < 32) Bc[(size_t)(m0 + tm) * GNUM + j] = acc[jj];
        else        Cc[(size_t)(m0 + tm) * GNUM + (j - 32)] = acc[jj];
    }
}

// ---------------------------------------------------------------------------
// Causal depthwise conv (K=4, left pad 3, resets per batch) + silu + split.
// Tile: 32 l-rows x 128 channels; smem holds 35 rows.
// out[l] = w0*in[l-3] + w1*in[l-2] + w2*in[l-1] + w3*in[l]
// ---------------------------------------------------------------------------
__global__ __launch_bounds__(256) void conv_silu_kernel(
    const float* __restrict__ xz, const float* __restrict__ conv_w,
    float* __restrict__ xs, float* __restrict__ zs)
{
    __shared__ float tile[35][128];
    __shared__ float wsh[4][128];

    const int tid = threadIdx.x;
    const int c0  = blockIdx.x * 128;
    const int l0  = blockIdx.y * 32;
    const int b   = blockIdx.z;

    for (int i = tid; i < 35 * 128; i += 256) {
        int r = i >> 7, c = i & 127;
        int l = l0 - 3 + r;
        tile[r][c] = (l >= 0) ? xz[((size_t)b * LSEQ + l) * CDIM + c0 + c] : 0.f;
    }
    for (int i = tid; i < 512; i += 256)
        wsh[i & 3][i >> 2] = conv_w[(size_t)(c0 + (i >> 2)) * 4 + (i & 3)];
    __syncthreads();

    for (int i = tid; i < 32 * 128; i += 256) {
        int r = i >> 7, c = i & 127;
        float v = tile[r][c]     * wsh[0][c]
                + tile[r + 1][c] * wsh[1][c]
                + tile[r + 2][c] * wsh[2][c]
                + tile[r + 3][c] * wsh[3][c];
        float s = v / (1.f + expf(-v));       // silu (applied to both halves)
        int cg = c0 + c;
        size_t row = (size_t)b * LSEQ + (l0 + r);
        if (cg < DGATE) xs[row * DGATE + cg] = s;
        else            zs[row * DGATE + (cg - DGATE)] = s;
    }
}

// ---------------------------------------------------------------------------
// SSM scan. One block per (b,g); 128 threads = one per d.
// h = dA*h + (dt*B_l)*x_l ;  y_l = C_l*h.   B/C staged in smem.
// ---------------------------------------------------------------------------
__global__ __launch_bounds__(128) void scan_kernel(
    const float* __restrict__ xs, const float* __restrict__ Bc,
    const float* __restrict__ Cc, const float* __restrict__ A_log,
    const float* __restrict__ dt_bias, float* __restrict__ ys)
{
    __shared__ float sB[LSEQ];
    __shared__ float sC[LSEQ];

    const int b   = blockIdx.x >> 5;
    const int g   = blockIdx.x & 31;
    const int tid = threadIdx.x;

    const float A  = -expf(A_log[g]);
    const float dt = log1pf(expf(dt_bias[g]));   // softplus
    const float dA = expf(dt * A);

    for (int l = tid; l < LSEQ; l += 128) {
        sB[l] = dt * Bc[((size_t)b * LSEQ + l) * GNUM + g];
        sC[l] = Cc[((size_t)b * LSEQ + l) * GNUM + g];
    }
    __syncthreads();

    size_t base = ((size_t)b * LSEQ) * DGATE + (size_t)g * DHEAD + tid;
    float h = 0.f;
#pragma unroll 8
    for (int l = 0; l < LSEQ; l++) {
        float xv = xs[base];
        h = fmaf(dA, h, sB[l] * xv);
        ys[base] = sC[l] * h;
        base += DGATE;
    }
}

// ---------------------------------------------------------------------------
// RMSNorm over head dim (128) + gate with silu(z). One warp per (b,l,g).
// ---------------------------------------------------------------------------
__global__ __launch_bounds__(256) void norm_gate_kernel(
    const float* __restrict__ ys, const float* __restrict__ zs,
    const float* __restrict__ norm_w, float* __restrict__ gated)
{
    const int grp  = blockIdx.x * 8 + (threadIdx.x >> 5);  // 0 .. B*L*G-1
    const int lane = threadIdx.x & 31;
    const int g    = grp & 31;
    const size_t bl = (size_t)(grp >> 5);
    const size_t off = bl * DGATE + (size_t)g * DHEAD + lane * 4;

    float4 y = *(const float4*)(ys + off);
    float ss = y.x * y.x + y.y * y.y + y.z * y.z + y.w * y.w;
#pragma unroll
    for (int s = 16; s; s >>= 1) ss += __shfl_xor_sync(0xffffffffu, ss, s);
    float scale = rsqrtf(ss * (1.f / 128.f) + 1e-6f);

    float4 nw = *(const float4*)(norm_w + lane * 4);
    float4 z4 = *(const float4*)(zs + off);
    float4 o;
    o.x = y.x * scale * nw.x * z4.x;
    o.y = y.y * scale * nw.y * z4.y;
    o.z = y.z * scale * nw.z * z4.z;
    o.w = y.w * scale * nw.w * z4.w;
    *(float4*)(gated + off) = o;
}

// ---------------------------------------------------------------------------
// Launch
// ---------------------------------------------------------------------------
extern "C" void kernel_launch(void* const* d_in, const int* in_sizes, int n_in,
                              void* d_out, int out_size)
{
    const float* hidden  = (const float*)d_in[0];
    const float* W_qkv   = (const float*)d_in[1];
    const float* W_b     = (const float*)d_in[2];
    const float* W_a     = (const float*)d_in[3];
    const float* conv_w  = (const float*)d_in[4];
    const float* W_out   = (const float*)d_in[5];
    const float* norm_w  = (const float*)d_in[6];
    const float* A_log   = (const float*)d_in[7];
    const float* dt_bias = (const float*)d_in[8];
    float* out = (float*)d_out;

    float *xz, *xs, *zs, *ysb, *Bc, *Cc;
    cudaGetSymbolAddress((void**)&xz,  g_xz);
    cudaGetSymbolAddress((void**)&xs,  g_xs);
    cudaGetSymbolAddress((void**)&zs,  g_zs);
    cudaGetSymbolAddress((void**)&ysb, g_ys);
    cudaGetSymbolAddress((void**)&Bc,  g_Bc);
    cudaGetSymbolAddress((void**)&Cc,  g_Cc);
    float* gt = xz;   // reuse: xz is dead after conv_silu_kernel

    const int M = BSZ * LSEQ;   // 8192

    // 1) B/C coefficient projections
    coeff_kernel<<<M / 32, 256>>>(hidden, W_b, W_a, Bc, Cc);

    // 2) xz = hidden @ W_qkv.T   [8192 x 8192], K=2560
    sgemm_nt<<<dim3(CDIM / 128, M / 128), 256>>>(hidden, W_qkv, xz, M, CDIM, HDIM);

    // 3) causal depthwise conv + silu + split
    conv_silu_kernel<<<dim3(CDIM / 128, LSEQ / 32, BSZ), 256>>>(xz, conv_w, xs, zs);

    // 4) SSM scan
    scan_kernel<<<BSZ * GNUM, 128>>>(xs, Bc, Cc, A_log, dt_bias, ysb);

    // 5) RMSNorm + gate (writes into the dead xz region)
    norm_gate_kernel<<<(M * GNUM) / 8, 256>>>(ysb, zs, norm_w, gt);

    // 6) out = gated @ W_out.T   [8192 x 2560], K=4096
    sgemm_nt<<<dim3(HDIM / 128, M / 128), 256>>>(gt, W_out, out, M, HDIM, DGATE);
}

// round 4
// speedup vs baseline: 1.8181x; 1.8181x over previous
#include <cuda_runtime.h>
#include <cuda_bf16.h>
#include <math.h>
#include <stdint.h>

// Problem constants
#define BSZ   2
#define LSEQ  4096
#define HDIM  2560
#define CDIM  8192      // D_INNER
#define GNUM  32
#define DHEAD 128
#define DGATE 4096
#define KCONV 4

// ---------------------------------------------------------------------------
// Scratch (static device globals; cudaMalloc is forbidden).
// g_xz (256 MB) is dead after the conv kernel; gated activation reuses it.
// ---------------------------------------------------------------------------
__device__ float g_xz[(size_t)BSZ * LSEQ * CDIM];       // pre-conv xz; later: gated
__device__ float g_xs[(size_t)BSZ * LSEQ * DGATE];      // silu(conv x half)
__device__ float g_zs[(size_t)BSZ * LSEQ * DGATE];      // silu(conv z half)
__device__ float g_ys[(size_t)BSZ * LSEQ * DGATE];      // scan output
__device__ float g_Bc[(size_t)BSZ * LSEQ * GNUM];
__device__ float g_Cc[(size_t)BSZ * LSEQ * GNUM];

// ---------------------------------------------------------------------------
// Tensor-core GEMM NT with bf16x3 split emulation of fp32:
//   C[M,N] = A[M,K] * B[N,K]^T  (all row-major fp32)
// a = a_hi + a_lo (bf16 limbs);  C += Ahi*Bhi + Ahi*Blo + Alo*Bhi  (fp32 acc)
// Block tile 128x128, BK=32, 256 threads (8 warps, each 32x64).
// mma.sync.aligned.m16n8k16.row.col.f32.bf16.bf16.f32
// Requires M%128==0, N%128==0, K%32==0.
// ---------------------------------------------------------------------------
#define MMA_BF16(c, a, b)                                                     \
    asm volatile(                                                             \
        "mma.sync.aligned.m16n8k16.row.col.f32.bf16.bf16.f32 "                \
        "{%0,%1,%2,%3},{%4,%5,%6,%7},{%8,%9},{%0,%1,%2,%3};"                  \
        : "+f"((c)[0]), "+f"((c)[1]), "+f"((c)[2]), "+f"((c)[3])              \
        : "r"((a)[0]), "r"((a)[1]), "r"((a)[2]), "r"((a)[3]),                 \
          "r"((b)[0]), "r"((b)[1]))

__global__ __launch_bounds__(256, 1) void gemm_nt_bf16x3(
    const float* __restrict__ A, const float* __restrict__ B,
    float* __restrict__ C, int M, int N, int K)
{
    // padded to 40 bf16 per row (80B) -> conflict-free fragment loads
    __shared__ __nv_bfloat16 sAhi[128][40];
    __shared__ __nv_bfloat16 sAlo[128][40];
    __shared__ __nv_bfloat16 sBhi[128][40];
    __shared__ __nv_bfloat16 sBlo[128][40];

    const int tid  = threadIdx.x;
    const int lane = tid & 31;
    const int wid  = tid >> 5;
    const int wm   = (wid & 3) * 32;   // warp M offset in tile
    const int wn   = (wid >> 2) * 64;  // warp N offset in tile
    const int grp  = lane >> 2;        // 0..7
    const int tg   = lane & 3;         // 0..3

    const float* Ag = A + (size_t)(blockIdx.y * 128) * K;
    const float* Bg = B + (size_t)(blockIdx.x * 128) * K;

    float4 ra[4], rb[4];
    float acc[2][8][4];
#pragma unroll
    for (int mt = 0; mt < 2; mt++)
#pragma unroll
        for (int nt = 0; nt < 8; nt++)
#pragma unroll
            for (int j = 0; j < 4; j++) acc[mt][nt][j] = 0.f;

    // prologue load (k0 = 0)
#pragma unroll
    for (int i = 0; i < 4; i++) {
        int id = tid + i * 256;
        int r = id >> 3, c = (id & 7) * 4;
        ra[i] = *(const float4*)(Ag + (size_t)r * K + c);
        rb[i] = *(const float4*)(Bg + (size_t)r * K + c);
    }

    for (int k0 = 0; k0 < K; k0 += 32) {
        const bool more = (k0 + 32 < K);
        __syncthreads();   // smem free (previous compute done)
        // store staged regs -> smem with bf16 hi/lo split
#pragma unroll
        for (int i = 0; i < 4; i++) {
            int id = tid + i * 256;
            int r = id >> 3, c = (id & 7) * 4;
            float va[4] = {ra[i].x, ra[i].y, ra[i].z, ra[i].w};
            float vb[4] = {rb[i].x, rb[i].y, rb[i].z, rb[i].w};
#pragma unroll
            for (int j = 0; j < 4; j++) {
                __nv_bfloat16 h = __float2bfloat16(va[j]);
                sAhi[r][c + j] = h;
                sAlo[r][c + j] = __float2bfloat16(va[j] - __bfloat162float(h));
                __nv_bfloat16 g2 = __float2bfloat16(vb[j]);
                sBhi[r][c + j] = g2;
                sBlo[r][c + j] = __float2bfloat16(vb[j] - __bfloat162float(g2));
            }
        }
        __syncthreads();

        // prefetch next K tile (hidden behind compute)
        if (more) {
#pragma unroll
            for (int i = 0; i < 4; i++) {
                int id = tid + i * 256;
                int r = id >> 3, c = (id & 7) * 4;
                ra[i] = *(const float4*)(Ag + (size_t)r * K + k0 + 32 + c);
                rb[i] = *(const float4*)(Bg + (size_t)r * K + k0 + 32 + c);
            }
        }

        // compute: 2 k-subs of 16
#pragma unroll
        for (int ks = 0; ks < 2; ks++) {
            const int kb = ks * 16 + tg * 2;
            uint32_t ahi[2][4], alo[2][4], bhi[8][2], blo[8][2];
#pragma unroll
            for (int mt = 0; mt < 2; mt++) {
                int r = wm + mt * 16 + grp;
                ahi[mt][0] = *(const uint32_t*)&sAhi[r][kb];
                ahi[mt][1] = *(const uint32_t*)&sAhi[r + 8][kb];
                ahi[mt][2] = *(const uint32_t*)&sAhi[r][kb + 8];
                ahi[mt][3] = *(const uint32_t*)&sAhi[r + 8][kb + 8];
                alo[mt][0] = *(const uint32_t*)&sAlo[r][kb];
                alo[mt][1] = *(const uint32_t*)&sAlo[r + 8][kb];
                alo[mt][2] = *(const uint32_t*)&sAlo[r][kb + 8];
                alo[mt][3] = *(const uint32_t*)&sAlo[r + 8][kb + 8];
            }
#pragma unroll
            for (int nt = 0; nt < 8; nt++) {
                int n = wn + nt * 8 + grp;
                bhi[nt][0] = *(const uint32_t*)&sBhi[n][kb];
                bhi[nt][1] = *(const uint32_t*)&sBhi[n][kb + 8];
                blo[nt][0] = *(const uint32_t*)&sBlo[n][kb];
                blo[nt][1] = *(const uint32_t*)&sBlo[n][kb + 8];
            }
            // hi*hi
#pragma unroll
            for (int mt = 0; mt < 2; mt++)
#pragma unroll
                for (int nt = 0; nt < 8; nt++) MMA_BF16(acc[mt][nt], ahi[mt], bhi[nt]);
            // hi*lo
#pragma unroll
            for (int mt = 0; mt < 2; mt++)
#pragma unroll
                for (int nt = 0; nt < 8; nt++) MMA_BF16(acc[mt][nt], ahi[mt], blo[nt]);
            // lo*hi
#pragma unroll
            for (int mt = 0; mt < 2; mt++)
#pragma unroll
                for (int nt = 0; nt < 8; nt++) MMA_BF16(acc[mt][nt], alo[mt], bhi[nt]);
        }
    }

    // epilogue
#pragma unroll
    for (int mt = 0; mt < 2; mt++) {
#pragma unroll
        for (int nt = 0; nt < 8; nt++) {
            size_t row = (size_t)blockIdx.y * 128 + wm + mt * 16 + grp;
            size_t col = (size_t)blockIdx.x * 128 + wn + nt * 8 + tg * 2;
            float* p = C + row * N + col;
            *(float2*)p = make_float2(acc[mt][nt][0], acc[mt][nt][1]);
            *(float2*)(p + 8 * (size_t)N) = make_float2(acc[mt][nt][2], acc[mt][nt][3]);
        }
    }
}

// ---------------------------------------------------------------------------
// B/C coefficient projections: [M,32] = hidden[M,2560] @ W_b.T, and W_a.T.
// ---------------------------------------------------------------------------
__global__ __launch_bounds__(256) void coeff_kernel(
    const float* __restrict__ hid, const float* __restrict__ Wb,
    const float* __restrict__ Wa, float* __restrict__ Bc, float* __restrict__ Cc)
{
    __shared__ float sh[32][65];
    __shared__ float sw[64][65];

    const int tid = threadIdx.x;
    const int m0  = blockIdx.x * 32;
    const int tm  = tid & 31;
    const int tj4 = tid >> 5;

    const int lr_h = tid >> 3;
    const int lc_h = (tid & 7) * 8;
    const int lr_w = tid >> 2;
    const int lc_w = (tid & 3) * 16;
    const float* wrow = (lr_w < 32) ? (Wb + (size_t)lr_w * HDIM)
                                    : (Wa + (size_t)(lr_w - 32) * HDIM);
    const float* hrow = hid + (size_t)(m0 + lr_h) * HDIM;

    float acc[8];
#pragma unroll
    for (int j = 0; j < 8; j++) acc[j] = 0.f;

    for (int k0 = 0; k0 < HDIM; k0 += 64) {
        __syncthreads();
#pragma unroll
        for (int i = 0; i < 8; i++)  sh[lr_h][lc_h + i] = hrow[k0 + lc_h + i];
#pragma unroll
        for (int i = 0; i < 16; i++) sw[lr_w][lc_w + i] = wrow[k0 + lc_w + i];
        __syncthreads();
#pragma unroll
        for (int k = 0; k < 64; k++) {
            float hv = sh[tm][k];
#pragma unroll
            for (int jj = 0; jj < 8; jj++)
                acc[jj] = fmaf(hv, sw[tj4 * 8 + jj][k], acc[jj]);
        }
    }

#pragma unroll
    for (int jj = 0; jj < 8; jj++) {
        int j = tj4 * 8 + jj;
        if (j < 32) Bc[(size_t)(m0 + tm) * GNUM + j] = acc[jj];
        else        Cc[(size_t)(m0 + tm) * GNUM + (j - 32)] = acc[jj];
    }
}

// ---------------------------------------------------------------------------
// Causal depthwise conv (K=4) + silu + split.
// ---------------------------------------------------------------------------
__global__ __launch_bounds__(256) void conv_silu_kernel(
    const float* __restrict__ xz, const float* __restrict__ conv_w,
    float* __restrict__ xs, float* __restrict__ zs)
{
    __shared__ float tile[35][128];
    __shared__ float wsh[4][128];

    const int tid = threadIdx.x;
    const int c0  = blockIdx.x * 128;
    const int l0  = blockIdx.y * 32;
    const int b   = blockIdx.z;

    for (int i = tid; i < 35 * 128; i += 256) {
        int r = i >> 7, c = i & 127;
        int l = l0 - 3 + r;
        tile[r][c] = (l >= 0) ? xz[((size_t)b * LSEQ + l) * CDIM + c0 + c] : 0.f;
    }
    for (int i = tid; i < 512; i += 256)
        wsh[i & 3][i >> 2] = conv_w[(size_t)(c0 + (i >> 2)) * 4 + (i & 3)];
    __syncthreads();

    for (int i = tid; i < 32 * 128; i += 256) {
        int r = i >> 7, c = i & 127;
        float v = tile[r][c]     * wsh[0][c]
                + tile[r + 1][c] * wsh[1][c]
                + tile[r + 2][c] * wsh[2][c]
                + tile[r + 3][c] * wsh[3][c];
        float s = v / (1.f + expf(-v));
        int cg = c0 + c;
        size_t row = (size_t)b * LSEQ + (l0 + r);
        if (cg < DGATE) xs[row * DGATE + cg] = s;
        else            zs[row * DGATE + (cg - DGATE)] = s;
    }
}

// ---------------------------------------------------------------------------
// SSM scan. One block per (b,g); 128 threads = one per d.
// ---------------------------------------------------------------------------
__global__ __launch_bounds__(128) void scan_kernel(
    const float* __restrict__ xs, const float* __restrict__ Bc,
    const float* __restrict__ Cc, const float* __restrict__ A_log,
    const float* __restrict__ dt_bias, float* __restrict__ ys)
{
    __shared__ float sB[LSEQ];
    __shared__ float sC[LSEQ];

    const int b   = blockIdx.x >> 5;
    const int g   = blockIdx.x & 31;
    const int tid = threadIdx.x;

    const float A  = -expf(A_log[g]);
    const float dt = log1pf(expf(dt_bias[g]));
    const float dA = expf(dt * A);

    for (int l = tid; l < LSEQ; l += 128) {
        sB[l] = dt * Bc[((size_t)b * LSEQ + l) * GNUM + g];
        sC[l] = Cc[((size_t)b * LSEQ + l) * GNUM + g];
    }
    __syncthreads();

    size_t base = ((size_t)b * LSEQ) * DGATE + (size_t)g * DHEAD + tid;
    float h = 0.f;
#pragma unroll 8
    for (int l = 0; l < LSEQ; l++) {
        float xv = xs[base];
        h = fmaf(dA, h, sB[l] * xv);
        ys[base] = sC[l] * h;
        base += DGATE;
    }
}

// ---------------------------------------------------------------------------
// RMSNorm over head dim (128) + gate with silu(z). One warp per (b,l,g).
// ---------------------------------------------------------------------------
__global__ __launch_bounds__(256) void norm_gate_kernel(
    const float* __restrict__ ys, const float* __restrict__ zs,
    const float* __restrict__ norm_w, float* __restrict__ gated)
{
    const int grp  = blockIdx.x * 8 + (threadIdx.x >> 5);
    const int lane = threadIdx.x & 31;
    const int g    = grp & 31;
    const size_t bl = (size_t)(grp >> 5);
    const size_t off = bl * DGATE + (size_t)g * DHEAD + lane * 4;

    float4 y = *(const float4*)(ys + off);
    float ss = y.x * y.x + y.y * y.y + y.z * y.z + y.w * y.w;
#pragma unroll
    for (int s = 16; s; s >>= 1) ss += __shfl_xor_sync(0xffffffffu, ss, s);
    float scale = rsqrtf(ss * (1.f / 128.f) + 1e-6f);

    float4 nw = *(const float4*)(norm_w + lane * 4);
    float4 z4 = *(const float4*)(zs + off);
    float4 o;
    o.x = y.x * scale * nw.x * z4.x;
    o.y = y.y * scale * nw.y * z4.y;
    o.z = y.z * scale * nw.z * z4.z;
    o.w = y.w * scale * nw.w * z4.w;
    *(float4*)(gated + off) = o;
}

// ---------------------------------------------------------------------------
// Launch
// ---------------------------------------------------------------------------
extern "C" void kernel_launch(void* const* d_in, const int* in_sizes, int n_in,
                              void* d_out, int out_size)
{
    const float* hidden  = (const float*)d_in[0];
    const float* W_qkv   = (const float*)d_in[1];
    const float* W_b     = (const float*)d_in[2];
    const float* W_a     = (const float*)d_in[3];
    const float* conv_w  = (const float*)d_in[4];
    const float* W_out   = (const float*)d_in[5];
    const float* norm_w  = (const float*)d_in[6];
    const float* A_log   = (const float*)d_in[7];
    const float* dt_bias = (const float*)d_in[8];
    float* out = (float*)d_out;

    float *xz, *xs, *zs, *ysb, *Bc, *Cc;
    cudaGetSymbolAddress((void**)&xz,  g_xz);
    cudaGetSymbolAddress((void**)&xs,  g_xs);
    cudaGetSymbolAddress((void**)&zs,  g_zs);
    cudaGetSymbolAddress((void**)&ysb, g_ys);
    cudaGetSymbolAddress((void**)&Bc,  g_Bc);
    cudaGetSymbolAddress((void**)&Cc,  g_Cc);
    float* gt = xz;   // reuse: xz dead after conv

    const int M = BSZ * LSEQ;   // 8192

    // 1) B/C coefficient projections
    coeff_kernel<<<M / 32, 256>>>(hidden, W_b, W_a, Bc, Cc);

    // 2) xz = hidden @ W_qkv.T  [8192 x 8192], K=2560  (tensor cores)
    gemm_nt_bf16x3<<<dim3(CDIM / 128, M / 128), 256>>>(hidden, W_qkv, xz, M, CDIM, HDIM);

    // 3) causal depthwise conv + silu + split
    conv_silu_kernel<<<dim3(CDIM / 128, LSEQ / 32, BSZ), 256>>>(xz, conv_w, xs, zs);

    // 4) SSM scan
    scan_kernel<<<BSZ * GNUM, 128>>>(xs, Bc, Cc, A_log, dt_bias, ysb);

    // 5) RMSNorm + gate
    norm_gate_kernel<<<(M * GNUM) / 8, 256>>>(ysb, zs, norm_w, gt);

    // 6) out = gated @ W_out.T  [8192 x 2560], K=4096  (tensor cores)
    gemm_nt_bf16x3<<<dim3(HDIM / 128, M / 128), 256>>>(gt, W_out, out, M, HDIM, DGATE);
}

// round 7
// speedup vs baseline: 3.0729x; 1.6902x over previous
#include <cuda_runtime.h>
#include <cuda_bf16.h>
#include <math.h>
#include <stdint.h>

// Problem constants
#define BSZ   2
#define LSEQ  4096
#define HDIM  2560
#define CDIM  8192      // D_INNER
#define GNUM  32
#define DHEAD 128
#define DGATE 4096

// ---------------------------------------------------------------------------
// Scratch (static device globals; cudaMalloc forbidden).
// ---------------------------------------------------------------------------
__device__ float g_xz[(size_t)BSZ * LSEQ * CDIM];   // 256 MB; ys overlays 2nd half
__device__ float g_xs[(size_t)BSZ * LSEQ * DGATE];  // 128 MB
__device__ float g_zs[(size_t)BSZ * LSEQ * DGATE];  // 128 MB
__device__ __align__(16) __nv_bfloat16 g_limb[88080384];  // 168 MB
__device__ float g_Bc[(size_t)BSZ * LSEQ * GNUM];
__device__ float g_Cc[(size_t)BSZ * LSEQ * GNUM];

// limb arena offsets (elements)
#define A1HI_OFF 0ull
#define A1LO_OFF 20971520ull
#define B1HI_OFF 41943040ull
#define B1LO_OFF 62914560ull
#define A2HI_OFF 0ull
#define A2LO_OFF 33554432ull
#define B2HI_OFF 67108864ull
#define B2LO_OFF 77594624ull

// ---------------------------------------------------------------------------
// PTX helpers (sm_100-safe: mma.sync + ldmatrix + cp.async only)
// ---------------------------------------------------------------------------
#define CP_ASYNC16(s, g) \
    asm volatile("cp.async.cg.shared.global [%0], [%1], 16;" :: "r"(s), "l"(g))

#define LDSM_X4(r0, r1, r2, r3, addr)                                       \
    asm volatile("ldmatrix.sync.aligned.m8n8.x4.shared.b16 {%0,%1,%2,%3}, [%4];" \
        : "=r"(r0), "=r"(r1), "=r"(r2), "=r"(r3) : "r"(addr))

#define MMA_BF16(c, a, b)                                                     \
    asm volatile(                                                             \
        "mma.sync.aligned.m16n8k16.row.col.f32.bf16.bf16.f32 "                \
        "{%0,%1,%2,%3},{%4,%5,%6,%7},{%8,%9},{%0,%1,%2,%3};"                  \
        : "+f"((c)[0]), "+f"((c)[1]), "+f"((c)[2]), "+f"((c)[3])              \
        : "r"((a)[0]), "r"((a)[1]), "r"((a)[2]), "r"((a)[3]),                 \
          "r"((b)[0]), "r"((b)[1]))

// ---------------------------------------------------------------------------
// HMMA GEMM NT, bf16x3 limbs: C[M,N] = A*B^T.
// A/B given as pre-split bf16 hi/lo limb tensors, K-major.
// Tile 128x128, K-chunk 64, 256 threads (8 warps a 32x64), double-buffered
// cp.async, ldmatrix fragment loads, SW128-swizzled smem.
// Requires M%128==0, N%128==0, K%64==0.
// ---------------------------------------------------------------------------
#define KCH 64
#define STG_BYTES (64 * 1024)
#define HG_SMEM   (2 * STG_BYTES)   // 131072 B

__global__ __launch_bounds__(256, 1) void hmma_gemm(
    const __nv_bfloat16* __restrict__ Ahi, const __nv_bfloat16* __restrict__ Alo,
    const __nv_bfloat16* __restrict__ Bhi, const __nv_bfloat16* __restrict__ Blo,
    float* __restrict__ C, int M, int N, int K)
{
    extern __shared__ __align__(128) char smem[];
    const uint32_t sb = (uint32_t)__cvta_generic_to_shared(smem);

    const int tid  = threadIdx.x;
    const int lane = tid & 31;
    const int wid  = tid >> 5;
    const int wm   = (wid & 3) * 32;
    const int wn   = (wid >> 2) * 64;
    const int bn = blockIdx.x, bm = blockIdx.y;

    const __nv_bfloat16* Agh = Ahi + (size_t)bm * 128 * K;
    const __nv_bfloat16* Agl = Alo + (size_t)bm * 128 * K;
    const __nv_bfloat16* Bgh = Bhi + (size_t)bn * 128 * K;
    const __nv_bfloat16* Bgl = Blo + (size_t)bn * 128 * K;

    float acc[2][8][4];
#pragma unroll
    for (int mt = 0; mt < 2; mt++)
#pragma unroll
        for (int nt = 0; nt < 8; nt++)
#pragma unroll
            for (int j = 0; j < 4; j++) acc[mt][nt][j] = 0.f;

    // stage layout: Ahi @0, Alo @16K, Bhi @32K, Blo @48K (each 128 rows x 128B)
    auto load_chunk = [&](int stage, int k0) {
        const uint32_t st = sb + stage * STG_BYTES;
#pragma unroll
        for (int i = 0; i < 4; i++) {
            int u = tid + i * 256;
            int r = u >> 3, c = u & 7;
            uint32_t off = (uint32_t)(r * 128 + c * 16);
            off ^= ((off >> 3) & 0x70);           // SW128 swizzle
            size_t go = (size_t)r * K + k0 + c * 8;
            CP_ASYNC16(st + off,         Agh + go);
            CP_ASYNC16(st + 16384 + off, Agl + go);
            CP_ASYNC16(st + 32768 + off, Bgh + go);
            CP_ASYNC16(st + 49152 + off, Bgl + go);
        }
    };

    const int nch = K / KCH;
    load_chunk(0, 0);
    asm volatile("cp.async.commit_group;" ::: "memory");

    // precomputed per-lane index pieces for ldmatrix addressing
    const int a_row = wm + (lane & 15);                 // + mt*16
    const int a_kb  = ((lane >> 4) << 4);               // + ks*32
    const int b_row = wn + (lane & 7) + ((lane >> 4) << 3);  // + p*16
    const int b_kb  = (((lane >> 3) & 1) << 4);         // + ks*32

    for (int k = 0; k < nch; k++) {
        const int cur = k & 1;
        if (k + 1 < nch) {
            load_chunk(cur ^ 1, (k + 1) * KCH);
            asm volatile("cp.async.commit_group;" ::: "memory");
            asm volatile("cp.async.wait_group 1;" ::: "memory");
        } else {
            asm volatile("cp.async.wait_group 0;" ::: "memory");
        }
        __syncthreads();

        const uint32_t st = sb + cur * STG_BYTES;
#pragma unroll
        for (int ks = 0; ks < 4; ks++) {
            uint32_t aHi[2][4], aLo[2][4], bHi[8][2], bLo[8][2];
#pragma unroll
            for (int mt = 0; mt < 2; mt++) {
                uint32_t off = (uint32_t)((a_row + mt * 16) * 128 + ks * 32 + a_kb);
                off ^= ((off >> 3) & 0x70);
                LDSM_X4(aHi[mt][0], aHi[mt][1], aHi[mt][2], aHi[mt][3], st + off);
                LDSM_X4(aLo[mt][0], aLo[mt][1], aLo[mt][2], aLo[mt][3],
                        st + 16384 + off);
            }
#pragma unroll
            for (int p = 0; p < 4; p++) {
                uint32_t off = (uint32_t)((b_row + p * 16) * 128 + ks * 32 + b_kb);
                off ^= ((off >> 3) & 0x70);
                LDSM_X4(bHi[2 * p][0], bHi[2 * p][1], bHi[2 * p + 1][0],
                        bHi[2 * p + 1][1], st + 32768 + off);
                LDSM_X4(bLo[2 * p][0], bLo[2 * p][1], bLo[2 * p + 1][0],
                        bLo[2 * p + 1][1], st + 49152 + off);
            }
            // hi*hi
#pragma unroll
            for (int mt = 0; mt < 2; mt++)
#pragma unroll
                for (int nt = 0; nt < 8; nt++) MMA_BF16(acc[mt][nt], aHi[mt], bHi[nt]);
            // hi*lo
#pragma unroll
            for (int mt = 0; mt < 2; mt++)
#pragma unroll
                for (int nt = 0; nt < 8; nt++) MMA_BF16(acc[mt][nt], aHi[mt], bLo[nt]);
            // lo*hi
#pragma unroll
            for (int mt = 0; mt < 2; mt++)
#pragma unroll
                for (int nt = 0; nt < 8; nt++) MMA_BF16(acc[mt][nt], aLo[mt], bHi[nt]);
        }
        __syncthreads();   // protect cur buffer before next iteration reloads it
    }

    // epilogue
    const int grp = lane >> 2, tg = lane & 3;
#pragma unroll
    for (int mt = 0; mt < 2; mt++) {
#pragma unroll
        for (int nt = 0; nt < 8; nt++) {
            size_t row = (size_t)bm * 128 + wm + mt * 16 + grp;
            size_t col = (size_t)bn * 128 + wn + nt * 8 + tg * 2;
            float* p = C + row * N + col;
            *(float2*)p = make_float2(acc[mt][nt][0], acc[mt][nt][1]);
            *(float2*)(p + 8 * (size_t)N) = make_float2(acc[mt][nt][2], acc[mt][nt][3]);
        }
    }
}

// ---------------------------------------------------------------------------
// fp32 -> bf16 hi/lo limb split (elementwise)
// ---------------------------------------------------------------------------
__global__ __launch_bounds__(256) void split_kernel(
    const float* __restrict__ in, __nv_bfloat16* __restrict__ hi,
    __nv_bfloat16* __restrict__ lo, int n4)
{
    for (int i = blockIdx.x * 256 + threadIdx.x; i < n4; i += gridDim.x * 256) {
        float4 v = ((const float4*)in)[i];
        __nv_bfloat16 h0 = __float2bfloat16(v.x), h1 = __float2bfloat16(v.y);
        __nv_bfloat16 h2 = __float2bfloat16(v.z), h3 = __float2bfloat16(v.w);
        __nv_bfloat162 ha; ha.x = h0; ha.y = h1;
        __nv_bfloat162 hb; hb.x = h2; hb.y = h3;
        __nv_bfloat162 la; la.x = __float2bfloat16(v.x - __bfloat162float(h0));
        la.y = __float2bfloat16(v.y - __bfloat162float(h1));
        __nv_bfloat162 lb; lb.x = __float2bfloat16(v.z - __bfloat162float(h2));
        lb.y = __float2bfloat16(v.w - __bfloat162float(h3));
        ((__nv_bfloat162*)hi)[2 * i]     = ha;
        ((__nv_bfloat162*)hi)[2 * i + 1] = hb;
        ((__nv_bfloat162*)lo)[2 * i]     = la;
        ((__nv_bfloat162*)lo)[2 * i + 1] = lb;
    }
}

// ---------------------------------------------------------------------------
// B/C coefficient projections
// ---------------------------------------------------------------------------
__global__ __launch_bounds__(256) void coeff_kernel(
    const float* __restrict__ hid, const float* __restrict__ Wb,
    const float* __restrict__ Wa, float* __restrict__ Bc, float* __restrict__ Cc)
{
    __shared__ float sh[32][65];
    __shared__ float sw[64][65];

    const int tid = threadIdx.x;
    const int m0  = blockIdx.x * 32;
    const int tm  = tid & 31;
    const int tj4 = tid >> 5;

    const int lr_h = tid >> 3;
    const int lc_h = (tid & 7) * 8;
    const int lr_w = tid >> 2;
    const int lc_w = (tid & 3) * 16;
    const float* wrow = (lr_w < 32) ? (Wb + (size_t)lr_w * HDIM)
                                    : (Wa + (size_t)(lr_w - 32) * HDIM);
    const float* hrow = hid + (size_t)(m0 + lr_h) * HDIM;

    float acc[8];
#pragma unroll
    for (int j = 0; j < 8; j++) acc[j] = 0.f;

    for (int k0 = 0; k0 < HDIM; k0 += 64) {
        __syncthreads();
#pragma unroll
        for (int i = 0; i < 8; i++)  sh[lr_h][lc_h + i] = hrow[k0 + lc_h + i];
#pragma unroll
        for (int i = 0; i < 16; i++) sw[lr_w][lc_w + i] = wrow[k0 + lc_w + i];
        __syncthreads();
#pragma unroll
        for (int k = 0; k < 64; k++) {
            float hv = sh[tm][k];
#pragma unroll
            for (int jj = 0; jj < 8; jj++)
                acc[jj] = fmaf(hv, sw[tj4 * 8 + jj][k], acc[jj]);
        }
    }

#pragma unroll
    for (int jj = 0; jj < 8; jj++) {
        int j = tj4 * 8 + jj;
        if (j < 32) Bc[(size_t)(m0 + tm) * GNUM + j] = acc[jj];
        else        Cc[(size_t)(m0 + tm) * GNUM + (j - 32)] = acc[jj];
    }
}

// ---------------------------------------------------------------------------
// Causal depthwise conv (K=4) + silu + split
// ---------------------------------------------------------------------------
__global__ __launch_bounds__(256) void conv_silu_kernel(
    const float* __restrict__ xz, const float* __restrict__ conv_w,
    float* __restrict__ xs, float* __restrict__ zs)
{
    __shared__ float tile[35][128];
    __shared__ float wsh[4][128];

    const int tid = threadIdx.x;
    const int c0  = blockIdx.x * 128;
    const int l0  = blockIdx.y * 32;
    const int b   = blockIdx.z;

    for (int i = tid; i < 35 * 128; i += 256) {
        int r = i >> 7, c = i & 127;
        int l = l0 - 3 + r;
        tile[r][c] = (l >= 0) ? xz[((size_t)b * LSEQ + l) * CDIM + c0 + c] : 0.f;
    }
    for (int i = tid; i < 512; i += 256)
        wsh[i & 3][i >> 2] = conv_w[(size_t)(c0 + (i >> 2)) * 4 + (i & 3)];
    __syncthreads();

    for (int i = tid; i < 32 * 128; i += 256) {
        int r = i >> 7, c = i & 127;
        float v = tile[r][c]     * wsh[0][c]
                + tile[r + 1][c] * wsh[1][c]
                + tile[r + 2][c] * wsh[2][c]
                + tile[r + 3][c] * wsh[3][c];
        float s = v / (1.f + expf(-v));
        int cg = c0 + c;
        size_t row = (size_t)b * LSEQ + (l0 + r);
        if (cg < DGATE) xs[row * DGATE + cg] = s;
        else            zs[row * DGATE + (cg - DGATE)] = s;
    }
}

// ---------------------------------------------------------------------------
// SSM scan
// ---------------------------------------------------------------------------
__global__ __launch_bounds__(128) void scan_kernel(
    const float* __restrict__ xs, const float* __restrict__ Bc,
    const float* __restrict__ Cc, const float* __restrict__ A_log,
    const float* __restrict__ dt_bias, float* __restrict__ ys)
{
    __shared__ float sB[LSEQ];
    __shared__ float sC[LSEQ];

    const int b   = blockIdx.x >> 5;
    const int g   = blockIdx.x & 31;
    const int tid = threadIdx.x;

    const float A  = -expf(A_log[g]);
    const float dt = log1pf(expf(dt_bias[g]));
    const float dA = expf(dt * A);

    for (int l = tid; l < LSEQ; l += 128) {
        sB[l] = dt * Bc[((size_t)b * LSEQ + l) * GNUM + g];
        sC[l] = Cc[((size_t)b * LSEQ + l) * GNUM + g];
    }
    __syncthreads();

    size_t base = ((size_t)b * LSEQ) * DGATE + (size_t)g * DHEAD + tid;
    float h = 0.f;
#pragma unroll 8
    for (int l = 0; l < LSEQ; l++) {
        float xv = xs[base];
        h = fmaf(dA, h, sB[l] * xv);
        ys[base] = sC[l] * h;
        base += DGATE;
    }
}

// ---------------------------------------------------------------------------
// RMSNorm + gate, emitting bf16 hi/lo limbs directly (A operand of GEMM2)
// ---------------------------------------------------------------------------
__global__ __launch_bounds__(256) void norm_gate_split_kernel(
    const float* __restrict__ ys, const float* __restrict__ zs,
    const float* __restrict__ norm_w,
    __nv_bfloat16* __restrict__ ghi, __nv_bfloat16* __restrict__ glo)
{
    const int grp  = blockIdx.x * 8 + (threadIdx.x >> 5);
    const int lane = threadIdx.x & 31;
    const int g    = grp & 31;
    const size_t bl = (size_t)(grp >> 5);
    const size_t off = bl * DGATE + (size_t)g * DHEAD + lane * 4;

    float4 y = *(const float4*)(ys + off);
    float ss = y.x * y.x + y.y * y.y + y.z * y.z + y.w * y.w;
#pragma unroll
    for (int s = 16; s; s >>= 1) ss += __shfl_xor_sync(0xffffffffu, ss, s);
    float scale = rsqrtf(ss * (1.f / 128.f) + 1e-6f);

    float4 nw = *(const float4*)(norm_w + lane * 4);
    float4 z4 = *(const float4*)(zs + off);
    float o[4];
    o[0] = y.x * scale * nw.x * z4.x;
    o[1] = y.y * scale * nw.y * z4.y;
    o[2] = y.z * scale * nw.z * z4.z;
    o[3] = y.w * scale * nw.w * z4.w;

    __nv_bfloat162 h01, h23, l01, l23;
    h01.x = __float2bfloat16(o[0]); h01.y = __float2bfloat16(o[1]);
    h23.x = __float2bfloat16(o[2]); h23.y = __float2bfloat16(o[3]);
    l01.x = __float2bfloat16(o[0] - __bfloat162float(h01.x));
    l01.y = __float2bfloat16(o[1] - __bfloat162float(h01.y));
    l23.x = __float2bfloat16(o[2] - __bfloat162float(h23.x));
    l23.y = __float2bfloat16(o[3] - __bfloat162float(h23.y));
    *(__nv_bfloat162*)(ghi + off)     = h01;
    *(__nv_bfloat162*)(ghi + off + 2) = h23;
    *(__nv_bfloat162*)(glo + off)     = l01;
    *(__nv_bfloat162*)(glo + off + 2) = l23;
}

// ---------------------------------------------------------------------------
// Launch
// ---------------------------------------------------------------------------
extern "C" void kernel_launch(void* const* d_in, const int* in_sizes, int n_in,
                              void* d_out, int out_size)
{
    const float* hidden  = (const float*)d_in[0];
    const float* W_qkv   = (const float*)d_in[1];
    const float* W_b     = (const float*)d_in[2];
    const float* W_a     = (const float*)d_in[3];
    const float* conv_w  = (const float*)d_in[4];
    const float* W_out   = (const float*)d_in[5];
    const float* norm_w  = (const float*)d_in[6];
    const float* A_log   = (const float*)d_in[7];
    const float* dt_bias = (const float*)d_in[8];
    float* out = (float*)d_out;

    float *xz, *xs, *zs, *Bc, *Cc;
    __nv_bfloat16* limb;
    cudaGetSymbolAddress((void**)&xz,   g_xz);
    cudaGetSymbolAddress((void**)&xs,   g_xs);
    cudaGetSymbolAddress((void**)&zs,   g_zs);
    cudaGetSymbolAddress((void**)&limb, g_limb);
    cudaGetSymbolAddress((void**)&Bc,   g_Bc);
    cudaGetSymbolAddress((void**)&Cc,   g_Cc);
    float* ysb = xz + (size_t)BSZ * LSEQ * DGATE;   // ys overlays 2nd half of xz

    cudaFuncSetAttribute(hmma_gemm, cudaFuncAttributeMaxDynamicSharedMemorySize,
                         HG_SMEM);

    const int M = BSZ * LSEQ;   // 8192

    // 1) B/C coefficient projections
    coeff_kernel<<<M / 32, 256>>>(hidden, W_b, W_a, Bc, Cc);

    // 2) limb splits for GEMM1 operands
    split_kernel<<<1184, 256>>>(hidden, limb + A1HI_OFF, limb + A1LO_OFF,
                                (int)((size_t)M * HDIM / 4));
    split_kernel<<<1184, 256>>>(W_qkv, limb + B1HI_OFF, limb + B1LO_OFF,
                                (int)((size_t)CDIM * HDIM / 4));

    // 3) xz = hidden @ W_qkv.T  [8192 x 8192], K=2560  (HMMA bf16x3)
    hmma_gemm<<<dim3(CDIM / 128, M / 128), 256, HG_SMEM>>>(
        limb + A1HI_OFF, limb + A1LO_OFF, limb + B1HI_OFF, limb + B1LO_OFF,
        xz, M, CDIM, HDIM);

    // 4) causal depthwise conv + silu + split
    conv_silu_kernel<<<dim3(CDIM / 128, LSEQ / 32, BSZ), 256>>>(xz, conv_w, xs, zs);

    // 5) SSM scan (writes into 2nd half of g_xz)
    scan_kernel<<<BSZ * GNUM, 128>>>(xs, Bc, Cc, A_log, dt_bias, ysb);

    // 6) RMSNorm + gate -> A2 limbs
    norm_gate_split_kernel<<<(M * GNUM) / 8, 256>>>(
        ysb, zs, norm_w, limb + A2HI_OFF, limb + A2LO_OFF);

    // 7) W_out limbs (region overlaps dead B1 limbs)
    split_kernel<<<1184, 256>>>(W_out, limb + B2HI_OFF, limb + B2LO_OFF,
                                (int)((size_t)HDIM * DGATE / 4));

    // 8) out = gated @ W_out.T  [8192 x 2560], K=4096  (HMMA bf16x3)
    hmma_gemm<<<dim3(HDIM / 128, M / 128), 256, HG_SMEM>>>(
        limb + A2HI_OFF, limb + A2LO_OFF, limb + B2HI_OFF, limb + B2LO_OFF,
        out, M, HDIM, DGATE);
}

// round 9
// speedup vs baseline: 3.4364x; 1.1183x over previous
#include <cuda_runtime.h>
#include <cuda_bf16.h>
#include <math.h>
#include <stdint.h>

// Problem constants
#define BSZ   2
#define LSEQ  4096
#define HDIM  2560
#define CDIM  8192      // D_INNER
#define GNUM  32
#define DHEAD 128
#define DGATE 4096

#define SCH      256                 // scan chunk length
#define NCH_SCAN (LSEQ / SCH)        // 16

// ---------------------------------------------------------------------------
// Scratch (static device globals; cudaMalloc forbidden).
// ---------------------------------------------------------------------------
__device__ float g_xz[(size_t)BSZ * LSEQ * CDIM];   // 256 MB; ys overlays 2nd half
__device__ float g_xs[(size_t)BSZ * LSEQ * DGATE];  // 128 MB
__device__ float g_zs[(size_t)BSZ * LSEQ * DGATE];  // 128 MB
__device__ __align__(16) __nv_bfloat16 g_limb[88080384];  // 168 MB
__device__ float g_Bc[(size_t)BSZ * LSEQ * GNUM];
__device__ float g_Cc[(size_t)BSZ * LSEQ * GNUM];
__device__ float g_S[(size_t)BSZ * GNUM * NCH_SCAN * DHEAD];  // 512 KB chunk states

// limb arena offsets (elements)
#define A1HI_OFF 0ull
#define A1LO_OFF 20971520ull
#define B1HI_OFF 41943040ull
#define B1LO_OFF 62914560ull
#define A2HI_OFF 0ull
#define A2LO_OFF 33554432ull
#define B2HI_OFF 67108864ull
#define B2LO_OFF 77594624ull

// ---------------------------------------------------------------------------
// PTX helpers (sm_100-safe: mma.sync + ldmatrix + cp.async only)
// ---------------------------------------------------------------------------
#define CP_ASYNC16(s, g) \
    asm volatile("cp.async.cg.shared.global [%0], [%1], 16;" :: "r"(s), "l"(g))

#define LDSM_X4(r0, r1, r2, r3, addr)                                       \
    asm volatile("ldmatrix.sync.aligned.m8n8.x4.shared.b16 {%0,%1,%2,%3}, [%4];" \
        : "=r"(r0), "=r"(r1), "=r"(r2), "=r"(r3) : "r"(addr))

#define MMA_BF16(c, a, b)                                                     \
    asm volatile(                                                             \
        "mma.sync.aligned.m16n8k16.row.col.f32.bf16.bf16.f32 "                \
        "{%0,%1,%2,%3},{%4,%5,%6,%7},{%8,%9},{%0,%1,%2,%3};"                  \
        : "+f"((c)[0]), "+f"((c)[1]), "+f"((c)[2]), "+f"((c)[3])              \
        : "r"((a)[0]), "r"((a)[1]), "r"((a)[2]), "r"((a)[3]),                 \
          "r"((b)[0]), "r"((b)[1]))

// ---------------------------------------------------------------------------
// HMMA GEMM NT, bf16x3 limbs: C[M,N] = A*B^T.
// Tile 128x128, K-chunk 64, 256 threads (8 warps a 32x64), 3-stage cp.async
// pipeline (single barrier per chunk), ldmatrix loads, SW128 swizzle.
// Requires M%128==0, N%128==0, K%64==0, K/64 >= 2.
// ---------------------------------------------------------------------------
#define KCH 64
#define STG_BYTES (64 * 1024)
#define HG_SMEM   (3 * STG_BYTES)   // 196608 B

__global__ __launch_bounds__(256, 1) void hmma_gemm(
    const __nv_bfloat16* __restrict__ Ahi, const __nv_bfloat16* __restrict__ Alo,
    const __nv_bfloat16* __restrict__ Bhi, const __nv_bfloat16* __restrict__ Blo,
    float* __restrict__ C, int M, int N, int K)
{
    extern __shared__ __align__(128) char smem[];
    const uint32_t sb = (uint32_t)__cvta_generic_to_shared(smem);

    const int tid  = threadIdx.x;
    const int lane = tid & 31;
    const int wid  = tid >> 5;
    const int wm   = (wid & 3) * 32;
    const int wn   = (wid >> 2) * 64;
    const int bn = blockIdx.x, bm = blockIdx.y;

    const __nv_bfloat16* Agh = Ahi + (size_t)bm * 128 * K;
    const __nv_bfloat16* Agl = Alo + (size_t)bm * 128 * K;
    const __nv_bfloat16* Bgh = Bhi + (size_t)bn * 128 * K;
    const __nv_bfloat16* Bgl = Blo + (size_t)bn * 128 * K;

    float acc[2][8][4];
#pragma unroll
    for (int mt = 0; mt < 2; mt++)
#pragma unroll
        for (int nt = 0; nt < 8; nt++)
#pragma unroll
            for (int j = 0; j < 4; j++) acc[mt][nt][j] = 0.f;

    // stage layout: Ahi @0, Alo @16K, Bhi @32K, Blo @48K (each 128 rows x 128B)
    auto load_chunk = [&](int stage, int k0) {
        const uint32_t st = sb + stage * STG_BYTES;
#pragma unroll
        for (int i = 0; i < 4; i++) {
            int u = tid + i * 256;
            int r = u >> 3, c = u & 7;
            uint32_t off = (uint32_t)(r * 128 + c * 16);
            off ^= ((off >> 3) & 0x70);           // SW128 swizzle
            size_t go = (size_t)r * K + k0 + c * 8;
            CP_ASYNC16(st + off,         Agh + go);
            CP_ASYNC16(st + 16384 + off, Agl + go);
            CP_ASYNC16(st + 32768 + off, Bgh + go);
            CP_ASYNC16(st + 49152 + off, Bgl + go);
        }
    };

    const int nch = K / KCH;
    load_chunk(0, 0);
    asm volatile("cp.async.commit_group;" ::: "memory");
    load_chunk(1, KCH);
    asm volatile("cp.async.commit_group;" ::: "memory");

    // precomputed per-lane index pieces for ldmatrix addressing
    const int a_row = wm + (lane & 15);                      // + mt*16
    const int a_kb  = ((lane >> 4) << 4);                    // + ks*32
    const int b_row = wn + (lane & 7) + ((lane >> 4) << 3);  // + p*16
    const int b_kb  = (((lane >> 3) & 1) << 4);              // + ks*32

    int stage = 0;
    for (int k = 0; k < nch; k++) {
        asm volatile("cp.async.wait_group 1;" ::: "memory");
        __syncthreads();   // chunk k resident & all warps done with stage buf

        const uint32_t st = sb + stage * STG_BYTES;
#pragma unroll
        for (int ks = 0; ks < 4; ks++) {
            uint32_t aHi[2][4], aLo[2][4], bHi[8][2], bLo[8][2];
#pragma unroll
            for (int mt = 0; mt < 2; mt++) {
                uint32_t off = (uint32_t)((a_row + mt * 16) * 128 + ks * 32 + a_kb);
                off ^= ((off >> 3) & 0x70);
                LDSM_X4(aHi[mt][0], aHi[mt][1], aHi[mt][2], aHi[mt][3], st + off);
                LDSM_X4(aLo[mt][0], aLo[mt][1], aLo[mt][2], aLo[mt][3],
                        st + 16384 + off);
            }
#pragma unroll
            for (int p = 0; p < 4; p++) {
                uint32_t off = (uint32_t)((b_row + p * 16) * 128 + ks * 32 + b_kb);
                off ^= ((off >> 3) & 0x70);
                LDSM_X4(bHi[2 * p][0], bHi[2 * p][1], bHi[2 * p + 1][0],
                        bHi[2 * p + 1][1], st + 32768 + off);
                LDSM_X4(bLo[2 * p][0], bLo[2 * p][1], bLo[2 * p + 1][0],
                        bLo[2 * p + 1][1], st + 49152 + off);
            }
#pragma unroll
            for (int mt = 0; mt < 2; mt++)
#pragma unroll
                for (int nt = 0; nt < 8; nt++) MMA_BF16(acc[mt][nt], aHi[mt], bHi[nt]);
#pragma unroll
            for (int mt = 0; mt < 2; mt++)
#pragma unroll
                for (int nt = 0; nt < 8; nt++) MMA_BF16(acc[mt][nt], aHi[mt], bLo[nt]);
#pragma unroll
            for (int mt = 0; mt < 2; mt++)
#pragma unroll
                for (int nt = 0; nt < 8; nt++) MMA_BF16(acc[mt][nt], aLo[mt], bHi[nt]);
        }

        if (k + 2 < nch) {
            int ns = stage + 2; if (ns >= 3) ns -= 3;
            load_chunk(ns, (k + 2) * KCH);
            asm volatile("cp.async.commit_group;" ::: "memory");
        } else {
            // keep wait_group accounting aligned (empty group)
            asm volatile("cp.async.commit_group;" ::: "memory");
        }
        if (++stage == 3) stage = 0;
    }

    // epilogue
    const int grp = lane >> 2, tg = lane & 3;
#pragma unroll
    for (int mt = 0; mt < 2; mt++) {
#pragma unroll
        for (int nt = 0; nt < 8; nt++) {
            size_t row = (size_t)bm * 128 + wm + mt * 16 + grp;
            size_t col = (size_t)bn * 128 + wn + nt * 8 + tg * 2;
            float* p = C + row * N + col;
            *(float2*)p = make_float2(acc[mt][nt][0], acc[mt][nt][1]);
            *(float2*)(p + 8 * (size_t)N) = make_float2(acc[mt][nt][2], acc[mt][nt][3]);
        }
    }
}

// ---------------------------------------------------------------------------
// fp32 -> bf16 hi/lo limb split (elementwise)
// ---------------------------------------------------------------------------
__global__ __launch_bounds__(256) void split_kernel(
    const float* __restrict__ in, __nv_bfloat16* __restrict__ hi,
    __nv_bfloat16* __restrict__ lo, int n4)
{
    for (int i = blockIdx.x * 256 + threadIdx.x; i < n4; i += gridDim.x * 256) {
        float4 v = ((const float4*)in)[i];
        __nv_bfloat16 h0 = __float2bfloat16(v.x), h1 = __float2bfloat16(v.y);
        __nv_bfloat16 h2 = __float2bfloat16(v.z), h3 = __float2bfloat16(v.w);
        __nv_bfloat162 ha; ha.x = h0; ha.y = h1;
        __nv_bfloat162 hb; hb.x = h2; hb.y = h3;
        __nv_bfloat162 la; la.x = __float2bfloat16(v.x - __bfloat162float(h0));
        la.y = __float2bfloat16(v.y - __bfloat162float(h1));
        __nv_bfloat162 lb; lb.x = __float2bfloat16(v.z - __bfloat162float(h2));
        lb.y = __float2bfloat16(v.w - __bfloat162float(h3));
        ((__nv_bfloat162*)hi)[2 * i]     = ha;
        ((__nv_bfloat162*)hi)[2 * i + 1] = hb;
        ((__nv_bfloat162*)lo)[2 * i]     = la;
        ((__nv_bfloat162*)lo)[2 * i + 1] = lb;
    }
}

// ---------------------------------------------------------------------------
// B/C coefficient projections
// ---------------------------------------------------------------------------
__global__ __launch_bounds__(256) void coeff_kernel(
    const float* __restrict__ hid, const float* __restrict__ Wb,
    const float* __restrict__ Wa, float* __restrict__ Bc, float* __restrict__ Cc)
{
    __shared__ float sh[32][65];
    __shared__ float sw[64][65];

    const int tid = threadIdx.x;
    const int m0  = blockIdx.x * 32;
    const int tm  = tid & 31;
    const int tj4 = tid >> 5;

    const int lr_h = tid >> 3;
    const int lc_h = (tid & 7) * 8;
    const int lr_w = tid >> 2;
    const int lc_w = (tid & 3) * 16;
    const float* wrow = (lr_w < 32) ? (Wb + (size_t)lr_w * HDIM)
                                    : (Wa + (size_t)(lr_w - 32) * HDIM);
    const float* hrow = hid + (size_t)(m0 + lr_h) * HDIM;

    float acc[8];
#pragma unroll
    for (int j = 0; j < 8; j++) acc[j] = 0.f;

    for (int k0 = 0; k0 < HDIM; k0 += 64) {
        __syncthreads();
#pragma unroll
        for (int i = 0; i < 8; i++)  sh[lr_h][lc_h + i] = hrow[k0 + lc_h + i];
#pragma unroll
        for (int i = 0; i < 16; i++) sw[lr_w][lc_w + i] = wrow[k0 + lc_w + i];
        __syncthreads();
#pragma unroll
        for (int k = 0; k < 64; k++) {
            float hv = sh[tm][k];
#pragma unroll
            for (int jj = 0; jj < 8; jj++)
                acc[jj] = fmaf(hv, sw[tj4 * 8 + jj][k], acc[jj]);
        }
    }

#pragma unroll
    for (int jj = 0; jj < 8; jj++) {
        int j = tj4 * 8 + jj;
        if (j < 32) Bc[(size_t)(m0 + tm) * GNUM + j] = acc[jj];
        else        Cc[(size_t)(m0 + tm) * GNUM + (j - 32)] = acc[jj];
    }
}

// ---------------------------------------------------------------------------
// Causal depthwise conv (K=4) + silu + split
// ---------------------------------------------------------------------------
__global__ __launch_bounds__(256) void conv_silu_kernel(
    const float* __restrict__ xz, const float* __restrict__ conv_w,
    float* __restrict__ xs, float* __restrict__ zs)
{
    __shared__ float tile[35][128];
    __shared__ float wsh[4][128];

    const int tid = threadIdx.x;
    const int c0  = blockIdx.x * 128;
    const int l0  = blockIdx.y * 32;
    const int b   = blockIdx.z;

    for (int i = tid; i < 35 * 128; i += 256) {
        int r = i >> 7, c = i & 127;
        int l = l0 - 3 + r;
        tile[r][c] = (l >= 0) ? xz[((size_t)b * LSEQ + l) * CDIM + c0 + c] : 0.f;
    }
    for (int i = tid; i < 512; i += 256)
        wsh[i & 3][i >> 2] = conv_w[(size_t)(c0 + (i >> 2)) * 4 + (i & 3)];
    __syncthreads();

    for (int i = tid; i < 32 * 128; i += 256) {
        int r = i >> 7, c = i & 127;
        float v = tile[r][c]     * wsh[0][c]
                + tile[r + 1][c] * wsh[1][c]
                + tile[r + 2][c] * wsh[2][c]
                + tile[r + 3][c] * wsh[3][c];
        float s = v / (1.f + expf(-v));
        int cg = c0 + c;
        size_t row = (size_t)b * LSEQ + (l0 + r);
        if (cg < DGATE) xs[row * DGATE + cg] = s;
        else            zs[row * DGATE + (cg - DGATE)] = s;
    }
}

// ---------------------------------------------------------------------------
// SSM scan, chunked two-phase (dA is time-invariant per group).
// Phase 1: per (b,g,chunk) compute chunk-local end state (h0=0).
// ---------------------------------------------------------------------------
__global__ __launch_bounds__(128) void scan_phase1(
    const float* __restrict__ xs, const float* __restrict__ Bc,
    const float* __restrict__ A_log, const float* __restrict__ dt_bias,
    float* __restrict__ S)
{
    __shared__ float sB[SCH];
    const int c = blockIdx.y;
    const int b = blockIdx.x >> 5, g = blockIdx.x & 31;
    const int tid = threadIdx.x;

    const float A  = -expf(A_log[g]);
    const float dt = log1pf(expf(dt_bias[g]));
    const float dA = expf(dt * A);
    const int l0 = c * SCH;

    for (int l = tid; l < SCH; l += 128)
        sB[l] = dt * Bc[((size_t)b * LSEQ + l0 + l) * GNUM + g];
    __syncthreads();

    size_t base = ((size_t)b * LSEQ + l0) * DGATE + (size_t)g * DHEAD + tid;
    float h = 0.f;
#pragma unroll 8
    for (int l = 0; l < SCH; l++) {
        h = fmaf(dA, h, sB[l] * xs[base]);
        base += DGATE;
    }
    S[((size_t)blockIdx.x * NCH_SCAN + c) * DHEAD + tid] = h;
}

// Phase 2: rebuild carry-in from chunk states, replay chunk, emit y.
__global__ __launch_bounds__(128) void scan_phase2(
    const float* __restrict__ xs, const float* __restrict__ Bc,
    const float* __restrict__ Cc, const float* __restrict__ A_log,
    const float* __restrict__ dt_bias, const float* __restrict__ S,
    float* __restrict__ ys)
{
    __shared__ float sB[SCH];
    __shared__ float sC[SCH];
    const int c = blockIdx.y;
    const int b = blockIdx.x >> 5, g = blockIdx.x & 31;
    const int tid = threadIdx.x;

    const float A  = -expf(A_log[g]);
    const float dt = log1pf(expf(dt_bias[g]));
    const float dA  = expf(dt * A);
    const float dAc = expf(dt * A * (float)SCH);   // dA^SCH
    const int l0 = c * SCH;

    for (int l = tid; l < SCH; l += 128) {
        sB[l] = dt * Bc[((size_t)b * LSEQ + l0 + l) * GNUM + g];
        sC[l] = Cc[((size_t)b * LSEQ + l0 + l) * GNUM + g];
    }
    __syncthreads();

    // carry-in = sum_{c'<c} dAc^{c-1-c'} * S[c']
    float h = 0.f;
    const float* Sp = S + (size_t)blockIdx.x * NCH_SCAN * DHEAD + tid;
    for (int cp = 0; cp < c; cp++)
        h = fmaf(dAc, h, Sp[(size_t)cp * DHEAD]);

    size_t base = ((size_t)b * LSEQ + l0) * DGATE + (size_t)g * DHEAD + tid;
#pragma unroll 8
    for (int l = 0; l < SCH; l++) {
        h = fmaf(dA, h, sB[l] * xs[base]);
        ys[base] = sC[l] * h;
        base += DGATE;
    }
}

// ---------------------------------------------------------------------------
// RMSNorm + gate, emitting bf16 hi/lo limbs directly (A operand of GEMM2)
// ---------------------------------------------------------------------------
__global__ __launch_bounds__(256) void norm_gate_split_kernel(
    const float* __restrict__ ys, const float* __restrict__ zs,
    const float* __restrict__ norm_w,
    __nv_bfloat16* __restrict__ ghi, __nv_bfloat16* __restrict__ glo)
{
    const int grp  = blockIdx.x * 8 + (threadIdx.x >> 5);
    const int lane = threadIdx.x & 31;
    const int g    = grp & 31;
    const size_t bl = (size_t)(grp >> 5);
    const size_t off = bl * DGATE + (size_t)g * DHEAD + lane * 4;

    float4 y = *(const float4*)(ys + off);
    float ss = y.x * y.x + y.y * y.y + y.z * y.z + y.w * y.w;
#pragma unroll
    for (int s = 16; s; s >>= 1) ss += __shfl_xor_sync(0xffffffffu, ss, s);
    float scale = rsqrtf(ss * (1.f / 128.f) + 1e-6f);

    float4 nw = *(const float4*)(norm_w + lane * 4);
    float4 z4 = *(const float4*)(zs + off);
    float o[4];
    o[0] = y.x * scale * nw.x * z4.x;
    o[1] = y.y * scale * nw.y * z4.y;
    o[2] = y.z * scale * nw.z * z4.z;
    o[3] = y.w * scale * nw.w * z4.w;

    __nv_bfloat162 h01, h23, l01, l23;
    h01.x = __float2bfloat16(o[0]); h01.y = __float2bfloat16(o[1]);
    h23.x = __float2bfloat16(o[2]); h23.y = __float2bfloat16(o[3]);
    l01.x = __float2bfloat16(o[0] - __bfloat162float(h01.x));
    l01.y = __float2bfloat16(o[1] - __bfloat162float(h01.y));
    l23.x = __float2bfloat16(o[2] - __bfloat162float(h23.x));
    l23.y = __float2bfloat16(o[3] - __bfloat162float(h23.y));
    *(__nv_bfloat162*)(ghi + off)     = h01;
    *(__nv_bfloat162*)(ghi + off + 2) = h23;
    *(__nv_bfloat162*)(glo + off)     = l01;
    *(__nv_bfloat162*)(glo + off + 2) = l23;
}

// ---------------------------------------------------------------------------
// Launch
// ---------------------------------------------------------------------------
extern "C" void kernel_launch(void* const* d_in, const int* in_sizes, int n_in,
                              void* d_out, int out_size)
{
    const float* hidden  = (const float*)d_in[0];
    const float* W_qkv   = (const float*)d_in[1];
    const float* W_b     = (const float*)d_in[2];
    const float* W_a     = (const float*)d_in[3];
    const float* conv_w  = (const float*)d_in[4];
    const float* W_out   = (const float*)d_in[5];
    const float* norm_w  = (const float*)d_in[6];
    const float* A_log   = (const float*)d_in[7];
    const float* dt_bias = (const float*)d_in[8];
    float* out = (float*)d_out;

    float *xz, *xs, *zs, *Bc, *Cc, *Sst;
    __nv_bfloat16* limb;
    cudaGetSymbolAddress((void**)&xz,   g_xz);
    cudaGetSymbolAddress((void**)&xs,   g_xs);
    cudaGetSymbolAddress((void**)&zs,   g_zs);
    cudaGetSymbolAddress((void**)&limb, g_limb);
    cudaGetSymbolAddress((void**)&Bc,   g_Bc);
    cudaGetSymbolAddress((void**)&Cc,   g_Cc);
    cudaGetSymbolAddress((void**)&Sst,  g_S);
    float* ysb = xz + (size_t)BSZ * LSEQ * DGATE;   // ys overlays 2nd half of xz

    cudaFuncSetAttribute(hmma_gemm, cudaFuncAttributeMaxDynamicSharedMemorySize,
                         HG_SMEM);

    const int M = BSZ * LSEQ;   // 8192

    // 1) B/C coefficient projections
    coeff_kernel<<<M / 32, 256>>>(hidden, W_b, W_a, Bc, Cc);

    // 2) limb splits for GEMM1 operands
    split_kernel<<<1184, 256>>>(hidden, limb + A1HI_OFF, limb + A1LO_OFF,
                                (int)((size_t)M * HDIM / 4));
    split_kernel<<<1184, 256>>>(W_qkv, limb + B1HI_OFF, limb + B1LO_OFF,
                                (int)((size_t)CDIM * HDIM / 4));

    // 3) xz = hidden @ W_qkv.T  [8192 x 8192], K=2560  (HMMA bf16x3)
    hmma_gemm<<<dim3(CDIM / 128, M / 128), 256, HG_SMEM>>>(
        limb + A1HI_OFF, limb + A1LO_OFF, limb + B1HI_OFF, limb + B1LO_OFF,
        xz, M, CDIM, HDIM);

    // 4) causal depthwise conv + silu + split
    conv_silu_kernel<<<dim3(CDIM / 128, LSEQ / 32, BSZ), 256>>>(xz, conv_w, xs, zs);

    // 5) SSM scan: two-phase chunked parallel scan
    scan_phase1<<<dim3(BSZ * GNUM, NCH_SCAN), 128>>>(xs, Bc, A_log, dt_bias, Sst);
    scan_phase2<<<dim3(BSZ * GNUM, NCH_SCAN), 128>>>(xs, Bc, Cc, A_log, dt_bias,
                                                     Sst, ysb);

    // 6) RMSNorm + gate -> A2 limbs
    norm_gate_split_kernel<<<(M * GNUM) / 8, 256>>>(
        ysb, zs, norm_w, limb + A2HI_OFF, limb + A2LO_OFF);

    // 7) W_out limbs (region overlaps dead B1 limbs)
    split_kernel<<<1184, 256>>>(W_out, limb + B2HI_OFF, limb + B2LO_OFF,
                                (int)((size_t)HDIM * DGATE / 4));

    // 8) out = gated @ W_out.T  [8192 x 2560], K=4096  (HMMA bf16x3)
    hmma_gemm<<<dim3(HDIM / 128, M / 128), 256, HG_SMEM>>>(
        limb + A2HI_OFF, limb + A2LO_OFF, limb + B2HI_OFF, limb + B2LO_OFF,
        out, M, HDIM, DGATE);
}